// round 1
// baseline (speedup 1.0000x reference)
#include <cuda_runtime.h>
#include <math.h>

// Problem constants
#define BB 4
#define NN 256
#define CC 256
#define HH 8
#define FF 64
#define HF 512   // H*F

// -------- device scratch (no allocations allowed) --------
__device__ float g_gl[BB * NN * HF];   // x @ W_l   [b, n, h*64+f]
__device__ float g_gr[BB * NN * HF];   // x @ W_r
__device__ float g_el[BB * NN * HH];   // dot(g_l[b,n,h,:], w)
__device__ float g_er[BB * NN * HH];   // dot(g_r[b,n,h,:], w)

// ============================================================
// K1: SGEMM  G = X[1024,256] @ W[256,512]   (z: 0 -> W_l, 1 -> W_r)
// 64x64 tile, BK=16, 256 threads, 4x4 microtile
// ============================================================
__global__ __launch_bounds__(256) void k_gemm(const float* __restrict__ X,
                                              const float* __restrict__ Wl,
                                              const float* __restrict__ Wr) {
    __shared__ float As[16][68];
    __shared__ float Bs[16][68];
    const int which = blockIdx.z;
    const float* W = which ? Wr : Wl;
    float* G = which ? g_gr : g_gl;

    const int t  = threadIdx.x;
    const int tx = t & 15;
    const int ty = t >> 4;
    const int m0 = blockIdx.y * 64;
    const int n0 = blockIdx.x * 64;

    float acc[4][4] = {};

    for (int k0 = 0; k0 < 256; k0 += 16) {
        // stage X tile (transposed) : each thread one float4 along k
        float4 xa = *(const float4*)(X + (m0 + (t >> 2)) * 256 + k0 + (t & 3) * 4);
        const int kk = (t & 3) * 4, mm = t >> 2;
        As[kk + 0][mm] = xa.x;
        As[kk + 1][mm] = xa.y;
        As[kk + 2][mm] = xa.z;
        As[kk + 3][mm] = xa.w;
        // stage W tile
        *(float4*)(&Bs[t >> 4][(t & 15) * 4]) =
            *(const float4*)(W + (k0 + (t >> 4)) * 512 + n0 + (t & 15) * 4);
        __syncthreads();

        #pragma unroll
        for (int k = 0; k < 16; k++) {
            float4 a4 = *(const float4*)(&As[k][ty * 4]);
            float4 b4 = *(const float4*)(&Bs[k][tx * 4]);
            float ar[4] = {a4.x, a4.y, a4.z, a4.w};
            float br[4] = {b4.x, b4.y, b4.z, b4.w};
            #pragma unroll
            for (int i = 0; i < 4; i++)
                #pragma unroll
                for (int j = 0; j < 4; j++)
                    acc[i][j] = fmaf(ar[i], br[j], acc[i][j]);
        }
        __syncthreads();
    }

    #pragma unroll
    for (int i = 0; i < 4; i++) {
        float4 o = make_float4(acc[i][0], acc[i][1], acc[i][2], acc[i][3]);
        *(float4*)(G + (m0 + ty * 4 + i) * 512 + n0 + tx * 4) = o;
    }
}

// ============================================================
// K1b: er/el = per-(b,n,h) dot of g with attn_w (64-length)
// 16384 dots total; one thread each.
// ============================================================
__global__ __launch_bounds__(256) void k_dotw(const float* __restrict__ attn_w) {
    const int idx = blockIdx.x * 256 + threadIdx.x;   // 0..16383
    const int which = idx >> 13;                      // 0: g_l->el, 1: g_r->er
    const int r = idx & 8191;                         // (b*256+n)*8 + h
    const float* G = which ? g_gr : g_gl;
    float* E = which ? g_er : g_el;
    const float* g = G + (r >> 3) * 512 + (r & 7) * 64;
    float s = 0.f;
    #pragma unroll 16
    for (int f = 0; f < 64; f++) s = fmaf(g[f], attn_w[f], s);
    E[r] = s;
}

// ============================================================
// K2: fused pairwise-score + head-softmax + aggregation
// Block handles (b, 4 consecutive i rows). 512 threads.
// Loops j in chunks of 16, staging g_l/g_r rows in smem.
// e = 0.6*(er_i + el_j) + 0.4 * sum_f |gr_i + gl_j| * w[f]
// a = softmax_h(masked e);   out[i] += a * g_r[j]
// ============================================================
#define IT 4          // i rows per block
#define JC 16         // j chunk
#define GLS 516       // padded stride (words) for gl / gri
#define ES 9          // padded stride for e/a (per (i,j) pair)

#define SMEM_FLOATS (IT*GLS + JC*GLS + JC*512 + 64*ES + 64*ES + 64 + 64 + JC*8 + IT*8)

__global__ __launch_bounds__(512, 2) void k_attn(const float* __restrict__ attn_w,
                                                 const int* __restrict__ adj,
                                                 float* __restrict__ out) {
    extern __shared__ float sm[];
    float* s_gri  = sm;                       // IT * 516
    float* s_gl   = s_gri + IT * GLS;         // 16 * 516
    float* s_gr   = s_gl  + JC * GLS;         // 16 * 512
    float* s_e    = s_gr  + JC * 512;         // 64 * 9
    float* s_a    = s_e   + 64 * ES;          // 64 * 9
    float* s_dinv = s_a   + 64 * ES;          // 64
    float* s_w    = s_dinv + 64;              // 64
    float* s_el   = s_w   + 64;               // 128
    float* s_er   = s_el  + JC * 8;           // 32

    const int t   = threadIdx.x;
    const int blk = blockIdx.x;               // 0..255
    const int b   = blk >> 6;
    const int i0  = (blk & 63) * IT;

    // phase-1 mapping: one (i_l, j_l, h) item per thread
    const int h1  = t >> 6;
    const int il1 = (t >> 4) & 3;
    const int jl1 = t & 15;
    // phase-2 mapping: one i row, 4 contiguous output floats per thread
    const int il2 = t >> 7;
    const int c4  = t & 127;
    const int h2  = c4 >> 4;

    const float* Gl = g_gl + b * NN * HF;
    const float* Gr = g_gr + b * NN * HF;

    // --- prologue: w, g_r[i-tile], er ---
    if (t < 64) s_w[t] = attn_w[t];
    {
        const int il = t >> 7, e4 = t & 127;
        float4 v = *(const float4*)(Gr + (i0 + il) * 512 + e4 * 4);
        *(float4*)(&s_gri[il * GLS + e4 * 4]) = v;
    }
    if (t < 32) s_er[t] = g_er[(b * NN + i0 + (t >> 3)) * 8 + (t & 7)];
    __syncthreads();

    const float er1 = s_er[il1 * 8 + h1];

    float acc0 = 0.f, acc1 = 0.f, acc2 = 0.f, acc3 = 0.f;

    for (int jc = 0; jc < NN / JC; jc++) {
        const int j0 = jc * JC;

        // --- stage gl/gr rows j0..j0+15 (coalesced, 8 float4 per thread) ---
        #pragma unroll
        for (int q = 0; q < 4; q++) {
            const int idx  = t + q * 512;      // 0..2047
            const int row  = idx >> 7;
            const int col4 = idx & 127;
            float4 vl = *(const float4*)(Gl + (j0 + row) * 512 + col4 * 4);
            float4 vr = *(const float4*)(Gr + (j0 + row) * 512 + col4 * 4);
            *(float4*)(&s_gl[row * GLS + col4 * 4]) = vl;
            *(float4*)(&s_gr[row * 512 + col4 * 4]) = vr;
        }
        if (t < JC * 8) s_el[t] = g_el[(b * NN + j0 + (t >> 3)) * 8 + (t & 7)];
        __syncthreads();

        // --- phase 1: pairwise score for (il1, j0+jl1, h1) ---
        {
            const float* gl = &s_gl[jl1 * GLS + h1 * 64];
            const float* gi = &s_gri[il1 * GLS + h1 * 64];
            float s = 0.f;
            #pragma unroll
            for (int f4 = 0; f4 < 16; f4++) {
                float4 a  = *(const float4*)(gi + f4 * 4);
                float4 bq = *(const float4*)(gl + f4 * 4);
                float4 w4 = *(const float4*)(&s_w[f4 * 4]);
                s = fmaf(fabsf(a.x + bq.x), w4.x, s);
                s = fmaf(fabsf(a.y + bq.y), w4.y, s);
                s = fmaf(fabsf(a.z + bq.z), w4.z, s);
                s = fmaf(fabsf(a.w + bq.w), w4.w, s);
            }
            float e = 0.6f * (er1 + s_el[jl1 * 8 + h1]) + 0.4f * s;
            const int adjv = adj[((i0 + il1) * NN + (j0 + jl1)) * HH + h1];
            if (adjv == 0) e = -1e30f;
            s_e[(il1 * JC + jl1) * ES + h1] = e;
            __syncthreads();

            // softmax over the 8 heads of this (i,j)
            const float* ev = &s_e[(il1 * JC + jl1) * ES];
            float m = ev[0];
            #pragma unroll
            for (int hh = 1; hh < 8; hh++) m = fmaxf(m, ev[hh]);
            const float p = __expf(e - m);
            s_a[(il1 * JC + jl1) * ES + h1] = p;
            __syncthreads();

            if (t < 64) {
                const float* pv = &s_a[t * ES];
                float ssum = pv[0] + pv[1] + pv[2] + pv[3] +
                             pv[4] + pv[5] + pv[6] + pv[7];
                s_dinv[t] = __fdividef(1.0f, ssum);
            }
            __syncthreads();

            s_a[(il1 * JC + jl1) * ES + h1] = p * s_dinv[il1 * JC + jl1];
            __syncthreads();
        }

        // --- phase 2: out[i] += a * g_r[j] over this chunk ---
        {
            const float* abase = &s_a[il2 * JC * ES + h2];
            #pragma unroll
            for (int jl = 0; jl < JC; jl++) {
                const float a  = abase[jl * ES];
                float4 g4 = *(const float4*)(&s_gr[jl * 512 + c4 * 4]);
                acc0 = fmaf(a, g4.x, acc0);
                acc1 = fmaf(a, g4.y, acc1);
                acc2 = fmaf(a, g4.z, acc2);
                acc3 = fmaf(a, g4.w, acc3);
            }
        }
        __syncthreads();   // protect s_gr/s_a before next staging
    }

    float4 o = make_float4(acc0, acc1, acc2, acc3);
    *(float4*)(out + (b * NN + i0 + il2) * 512 + c4 * 4) = o;
}

// ============================================================
extern "C" void kernel_launch(void* const* d_in, const int* in_sizes, int n_in,
                              void* d_out, int out_size) {
    (void)in_sizes; (void)n_in; (void)out_size;
    const float* x    = (const float*)d_in[0];   // [4,256,256]
    const float* Wl   = (const float*)d_in[1];   // [256,512]
    const float* Wr   = (const float*)d_in[2];   // [256,512]
    const float* aw   = (const float*)d_in[3];   // [64]
    const int*   adj  = (const int*)d_in[4];     // [256,256,8]
    float*       out  = (float*)d_out;           // [4,256,512]

    // g_l, g_r
    k_gemm<<<dim3(8, 16, 2), 256>>>(x, Wl, Wr);
    // er, el
    k_dotw<<<64, 256>>>(aw);
    // fused attention
    const int smem_bytes = SMEM_FLOATS * (int)sizeof(float);
    cudaFuncSetAttribute(k_attn, cudaFuncAttributeMaxDynamicSharedMemorySize, smem_bytes);
    k_attn<<<256, 512, smem_bytes>>>(aw, adj, out);
}

// round 2
// speedup vs baseline: 1.2073x; 1.2073x over previous
#include <cuda_runtime.h>
#include <math.h>

// Problem constants
#define BB 4
#define NN 256
#define CC 256
#define HH 8
#define FF 64
#define HF 512   // H*F

typedef unsigned long long ull;

// -------- device scratch --------
__device__ float g_gl[BB * NN * HF];
__device__ float g_gr[BB * NN * HF];
__device__ float g_el[BB * NN * HH];
__device__ float g_er[BB * NN * HH];

// ---- packed f32x2 helpers ----
__device__ __forceinline__ ull f2add(ull a, ull b) {
    ull r; asm("add.rn.f32x2 %0,%1,%2;" : "=l"(r) : "l"(a), "l"(b)); return r;
}
__device__ __forceinline__ ull f2fma(ull a, ull b, ull c) {
    ull r; asm("fma.rn.f32x2 %0,%1,%2,%3;" : "=l"(r) : "l"(a), "l"(b), "l"(c)); return r;
}
__device__ __forceinline__ ull pk(float lo, float hi) {
    ull r; asm("mov.b64 %0,{%1,%2};" : "=l"(r) : "f"(lo), "f"(hi)); return r;
}
__device__ __forceinline__ float2 upk(ull v) {
    float2 r; asm("mov.b64 {%0,%1},%2;" : "=f"(r.x), "=f"(r.y) : "l"(v)); return r;
}

// ============================================================
// K1: SGEMM  G = X[1024,256] @ W[256,512]   (z: 0->W_l, 1->W_r)
// 32x64 tile, BK=16, 256 threads, 2x4 microtile. Fused epilogue
// computes per-(row,head) dot with attn_w into g_el / g_er.
// ============================================================
__global__ __launch_bounds__(256) void k_gemm(const float* __restrict__ X,
                                              const float* __restrict__ Wl,
                                              const float* __restrict__ Wr,
                                              const float* __restrict__ attn_w) {
    __shared__ float As[16][34];
    __shared__ float Bs[16][68];
    const int which = blockIdx.z;
    const float* W = which ? Wr : Wl;
    float* G = which ? g_gr : g_gl;
    float* E = which ? g_er : g_el;

    const int t  = threadIdx.x;
    const int tx = t & 15;
    const int ty = t >> 4;
    const int m0 = blockIdx.y * 32;
    const int n0 = blockIdx.x * 64;

    float acc[2][4] = {};

    for (int k0 = 0; k0 < 256; k0 += 16) {
        if (t < 128) {
            const int m = t >> 2, kq = t & 3;
            float4 xa = *(const float4*)(X + (m0 + m) * 256 + k0 + kq * 4);
            As[kq * 4 + 0][m] = xa.x;
            As[kq * 4 + 1][m] = xa.y;
            As[kq * 4 + 2][m] = xa.z;
            As[kq * 4 + 3][m] = xa.w;
        }
        {
            const int k = t >> 4, c = t & 15;
            *(float4*)(&Bs[k][c * 4]) =
                *(const float4*)(W + (k0 + k) * 512 + n0 + c * 4);
        }
        __syncthreads();
        #pragma unroll
        for (int k = 0; k < 16; k++) {
            float2 a2 = *(const float2*)(&As[k][ty * 2]);
            float4 b4 = *(const float4*)(&Bs[k][tx * 4]);
            float ar[2] = {a2.x, a2.y};
            float br[4] = {b4.x, b4.y, b4.z, b4.w};
            #pragma unroll
            for (int i = 0; i < 2; i++)
                #pragma unroll
                for (int j = 0; j < 4; j++)
                    acc[i][j] = fmaf(ar[i], br[j], acc[i][j]);
        }
        __syncthreads();
    }

    #pragma unroll
    for (int i = 0; i < 2; i++) {
        float4 o = make_float4(acc[i][0], acc[i][1], acc[i][2], acc[i][3]);
        *(float4*)(G + (m0 + ty * 2 + i) * 512 + n0 + tx * 4) = o;
    }

    // fused dot(g_row_head, attn_w)
    const int hh = n0 >> 6;
    float w0 = attn_w[tx * 4 + 0], w1 = attn_w[tx * 4 + 1];
    float w2 = attn_w[tx * 4 + 2], w3 = attn_w[tx * 4 + 3];
    #pragma unroll
    for (int i = 0; i < 2; i++) {
        float part = acc[i][0] * w0;
        part = fmaf(acc[i][1], w1, part);
        part = fmaf(acc[i][2], w2, part);
        part = fmaf(acc[i][3], w3, part);
        part += __shfl_xor_sync(0xffffffff, part, 8);
        part += __shfl_xor_sync(0xffffffff, part, 4);
        part += __shfl_xor_sync(0xffffffff, part, 2);
        part += __shfl_xor_sync(0xffffffff, part, 1);
        if (tx == 0) E[(m0 + ty * 2 + i) * 8 + hh] = part;
    }
}

// ============================================================
// K2: fused pairwise-score + head-softmax + aggregation
// 1024 threads, IT=8 i-rows/block, JC=16 j-chunk, 128 blocks.
// Phase1 warps are head-major; packed f32x2 math.
// ============================================================
#define IT 8
#define JC 16
#define JS 68            // per-row stride (words) in s_gl/s_gri
#define HSJ (JC*JS)      // 1088
#define HSI (IT*JS)      // 544
#define AS 9

#define SMEM_FLOATS (8*HSI + 8*HSJ + JC*512 + 128*AS + 128*AS + 64 + 128 + 64)

__global__ __launch_bounds__(1024, 1) void k_attn(const float* __restrict__ attn_w,
                                                  const int* __restrict__ adj,
                                                  float* __restrict__ out) {
    extern __shared__ float sm[];
    float* s_gri = sm;                     // 8*544
    float* s_gl  = s_gri + 8 * HSI;        // 8*1088
    float* s_gr  = s_gl + 8 * HSJ;         // 16*512
    float* s_e   = s_gr + JC * 512;        // 128*9
    float* s_a   = s_e + 128 * AS;         // 128*9
    float* s_w   = s_a + 128 * AS;         // 64
    float* s_el  = s_w + 64;               // 128
    float* s_er  = s_el + 128;             // 64
    float* s_red = s_gl;                   // aliased final-reduce buffer

    const int t = threadIdx.x;
    const int b = blockIdx.x >> 5;
    const int i0 = (blockIdx.x & 31) * IT;

    const float* Gl = g_gl + b * NN * HF;
    const float* Gr = g_gr + b * NN * HF;

    // phase-1 ids (head-major warps)
    const int w  = t >> 5, lane = t & 31;
    const int h1 = w >> 2;
    const int il1 = ((w & 3) << 1) | (lane >> 4);
    const int jl1 = lane & 15;
    // phase-2 ids
    const int c4  = t & 127;
    const int ilp = (t >> 7) & 3;
    const int jh  = t >> 9;
    const int h2  = c4 >> 4;

    // prologue
    if (t < 64) s_w[t] = attn_w[t];
    {
        const int il = t >> 7, rest = t & 127, h = rest >> 4, f4 = rest & 15;
        float4 v = *(const float4*)(Gr + (i0 + il) * 512 + rest * 4);
        *(float4*)(s_gri + h * HSI + il * JS + f4 * 4) = v;
    }
    if (t < 64) s_er[t] = g_er[(b * NN + i0 + (t >> 3)) * 8 + (t & 7)];
    __syncthreads();
    const float er1 = s_er[il1 * 8 + h1];

    const ull ABSM = 0x7FFFFFFF7FFFFFFFULL;
    const float* gi = s_gri + h1 * HSI + il1 * JS;
    const float* gl = s_gl + h1 * HSJ + jl1 * JS;

    ull acc[2][2] = {{0ULL, 0ULL}, {0ULL, 0ULL}};

    for (int jc = 0; jc < NN / JC; jc++) {
        const int j0 = jc * JC;

        // --- stage j-chunk ---
        #pragma unroll
        for (int q = 0; q < 2; q++) {
            const int idx4 = q * 1024 + t;
            const int jl = idx4 >> 7, rest = idx4 & 127;
            const int h = rest >> 4, f4 = rest & 15;
            float4 vl = *(const float4*)(Gl + (j0 + jl) * 512 + rest * 4);
            float4 vr = *(const float4*)(Gr + (j0 + jl) * 512 + rest * 4);
            *(float4*)(s_gl + h * HSJ + jl * JS + f4 * 4) = vl;
            *(float4*)(s_gr + jl * 512 + rest * 4) = vr;
        }
        if (t < 128) s_el[t] = g_el[(b * NN + j0 + (t >> 3)) * 8 + (t & 7)];
        __syncthreads();

        // --- phase 1: e[il1, j0+jl1, h1] ---
        {
            ull s0 = 0ULL, s1 = 0ULL;
            #pragma unroll
            for (int f4 = 0; f4 < 16; f4++) {
                ulonglong2 A  = *(const ulonglong2*)(gi + f4 * 4);
                ulonglong2 Bv = *(const ulonglong2*)(gl + f4 * 4);
                ulonglong2 Wv = *(const ulonglong2*)(s_w + f4 * 4);
                ull v0 = f2add(A.x, Bv.x) & ABSM;
                ull v1 = f2add(A.y, Bv.y) & ABSM;
                s0 = f2fma(v0, Wv.x, s0);
                s1 = f2fma(v1, Wv.y, s1);
            }
            float2 p0 = upk(s0), p1 = upk(s1);
            float s = (p0.x + p0.y) + (p1.x + p1.y);
            float e = 0.6f * (er1 + s_el[jl1 * 8 + h1]) + 0.4f * s;
            const int av = adj[((i0 + il1) * NN + (j0 + jl1)) * HH + h1];
            e = av ? e : -1e30f;
            s_e[(il1 * 16 + jl1) * AS + h1] = e;
        }
        __syncthreads();

        // --- softmax over heads, one thread per (il,jl) pair ---
        if (t < 128) {
            float ev[8];
            #pragma unroll
            for (int hh = 0; hh < 8; hh++) ev[hh] = s_e[t * AS + hh];
            float m = ev[0];
            #pragma unroll
            for (int hh = 1; hh < 8; hh++) m = fmaxf(m, ev[hh]);
            float ps[8]; float sum = 0.f;
            #pragma unroll
            for (int hh = 0; hh < 8; hh++) { ps[hh] = __expf(ev[hh] - m); sum += ps[hh]; }
            float rinv = __fdividef(1.0f, sum);
            #pragma unroll
            for (int hh = 0; hh < 8; hh++) s_a[t * AS + hh] = ps[hh] * rinv;
        }
        __syncthreads();

        // --- phase 2: out accumulation (this thread: il=ilp & ilp+4, j-half jh) ---
        {
            const int jbase = jh * 8;
            #pragma unroll
            for (int jq = 0; jq < 8; jq++) {
                const int jl = jbase + jq;
                ulonglong2 g = *(const ulonglong2*)(s_gr + jl * 512 + c4 * 4);
                float a0 = s_a[(ilp * 16 + jl) * AS + h2];
                float a1 = s_a[((ilp + 4) * 16 + jl) * AS + h2];
                ull pa0 = pk(a0, a0), pa1 = pk(a1, a1);
                acc[0][0] = f2fma(pa0, g.x, acc[0][0]);
                acc[0][1] = f2fma(pa0, g.y, acc[0][1]);
                acc[1][0] = f2fma(pa1, g.x, acc[1][0]);
                acc[1][1] = f2fma(pa1, g.y, acc[1][1]);
            }
        }
        __syncthreads();   // protect s_gl/s_gr/s_a before restaging
    }

    // --- cross j-half reduce + store ---
    if (jh == 1) {
        ull* dst = (ull*)s_red + (ilp * 128 + c4) * 4;
        dst[0] = acc[0][0]; dst[1] = acc[0][1];
        dst[2] = acc[1][0]; dst[3] = acc[1][1];
    }
    __syncthreads();
    if (jh == 0) {
        const ull* src = (const ull*)s_red + (ilp * 128 + c4) * 4;
        float2 r00 = upk(f2add(acc[0][0], src[0]));
        float2 r01 = upk(f2add(acc[0][1], src[1]));
        float2 r10 = upk(f2add(acc[1][0], src[2]));
        float2 r11 = upk(f2add(acc[1][1], src[3]));
        const int row0 = b * NN + i0 + ilp;
        const int row1 = b * NN + i0 + ilp + 4;
        *(float4*)(out + row0 * 512 + c4 * 4) = make_float4(r00.x, r00.y, r01.x, r01.y);
        *(float4*)(out + row1 * 512 + c4 * 4) = make_float4(r10.x, r10.y, r11.x, r11.y);
    }
}

// ============================================================
extern "C" void kernel_launch(void* const* d_in, const int* in_sizes, int n_in,
                              void* d_out, int out_size) {
    (void)in_sizes; (void)n_in; (void)out_size;
    const float* x   = (const float*)d_in[0];
    const float* Wl  = (const float*)d_in[1];
    const float* Wr  = (const float*)d_in[2];
    const float* aw  = (const float*)d_in[3];
    const int*   adj = (const int*)d_in[4];
    float*       out = (float*)d_out;

    k_gemm<<<dim3(8, 32, 2), 256>>>(x, Wl, Wr, aw);

    const int smem_bytes = SMEM_FLOATS * (int)sizeof(float);
    cudaFuncSetAttribute(k_attn, cudaFuncAttributeMaxDynamicSharedMemorySize, smem_bytes);
    k_attn<<<128, 1024, smem_bytes>>>(aw, adj, out);
}

// round 3
// speedup vs baseline: 1.4843x; 1.2294x over previous
#include <cuda_runtime.h>
#include <math.h>

#define BB 4
#define NN 256
#define CC 256
#define HH 8
#define FF 64
#define HF 512

typedef unsigned long long ull;

__device__ float g_gl[BB * NN * HF];
__device__ float g_gr[BB * NN * HF];
__device__ float g_el[BB * NN * HH];
__device__ float g_er[BB * NN * HH];

// ---- packed f32x2 helpers ----
__device__ __forceinline__ ull f2add(ull a, ull b) {
    ull r; asm("add.rn.f32x2 %0,%1,%2;" : "=l"(r) : "l"(a), "l"(b)); return r;
}
__device__ __forceinline__ ull f2fma(ull a, ull b, ull c) {
    ull r; asm("fma.rn.f32x2 %0,%1,%2,%3;" : "=l"(r) : "l"(a), "l"(b), "l"(c)); return r;
}
__device__ __forceinline__ ull pk(float lo, float hi) {
    ull r; asm("mov.b64 %0,{%1,%2};" : "=l"(r) : "f"(lo), "f"(hi)); return r;
}
__device__ __forceinline__ float2 upk(ull v) {
    float2 r; asm("mov.b64 {%0,%1},%2;" : "=f"(r.x), "=f"(r.y) : "l"(v)); return r;
}

// ============================================================
// K1: SGEMM G = X[1024,256] @ W[256,512] (z 0->l,1->r), 32x64 tile,
// packed f32x2 inner product, fused attn_w dot epilogue.
// ============================================================
__global__ __launch_bounds__(256) void k_gemm(const float* __restrict__ X,
                                              const float* __restrict__ Wl,
                                              const float* __restrict__ Wr,
                                              const float* __restrict__ attn_w) {
    __shared__ float As[16][34];
    __shared__ float Bs[16][68];
    const int which = blockIdx.z;
    const float* W = which ? Wr : Wl;
    float* G = which ? g_gr : g_gl;
    float* E = which ? g_er : g_el;

    const int t  = threadIdx.x;
    const int tx = t & 15;
    const int ty = t >> 4;
    const int m0 = blockIdx.y * 32;
    const int n0 = blockIdx.x * 64;

    ull acc[2][2] = {{0ULL,0ULL},{0ULL,0ULL}};

    for (int k0 = 0; k0 < 256; k0 += 16) {
        if (t < 128) {
            const int m = t >> 2, kq = t & 3;
            float4 xa = *(const float4*)(X + (m0 + m) * 256 + k0 + kq * 4);
            As[kq * 4 + 0][m] = xa.x;
            As[kq * 4 + 1][m] = xa.y;
            As[kq * 4 + 2][m] = xa.z;
            As[kq * 4 + 3][m] = xa.w;
        }
        {
            const int k = t >> 4, c = t & 15;
            *(float4*)(&Bs[k][c * 4]) =
                *(const float4*)(W + (k0 + k) * 512 + n0 + c * 4);
        }
        __syncthreads();
        #pragma unroll
        for (int k = 0; k < 16; k++) {
            float2 a2 = *(const float2*)(&As[k][ty * 2]);
            ulonglong2 b2 = *(const ulonglong2*)(&Bs[k][tx * 4]);
            ull pa0 = pk(a2.x, a2.x), pa1 = pk(a2.y, a2.y);
            acc[0][0] = f2fma(pa0, b2.x, acc[0][0]);
            acc[0][1] = f2fma(pa0, b2.y, acc[0][1]);
            acc[1][0] = f2fma(pa1, b2.x, acc[1][0]);
            acc[1][1] = f2fma(pa1, b2.y, acc[1][1]);
        }
        __syncthreads();
    }

    float af[2][4];
    #pragma unroll
    for (int i = 0; i < 2; i++) {
        float2 lo = upk(acc[i][0]), hi = upk(acc[i][1]);
        af[i][0] = lo.x; af[i][1] = lo.y; af[i][2] = hi.x; af[i][3] = hi.y;
        *(float4*)(G + (m0 + ty * 2 + i) * 512 + n0 + tx * 4) =
            make_float4(lo.x, lo.y, hi.x, hi.y);
    }

    const int hh = n0 >> 6;
    float w0 = attn_w[tx * 4 + 0], w1 = attn_w[tx * 4 + 1];
    float w2 = attn_w[tx * 4 + 2], w3 = attn_w[tx * 4 + 3];
    #pragma unroll
    for (int i = 0; i < 2; i++) {
        float part = af[i][0] * w0;
        part = fmaf(af[i][1], w1, part);
        part = fmaf(af[i][2], w2, part);
        part = fmaf(af[i][3], w3, part);
        part += __shfl_xor_sync(0xffffffff, part, 8);
        part += __shfl_xor_sync(0xffffffff, part, 4);
        part += __shfl_xor_sync(0xffffffff, part, 2);
        part += __shfl_xor_sync(0xffffffff, part, 1);
        if (tx == 0) E[(m0 + ty * 2 + i) * 8 + hh] = part;
    }
}

// ============================================================
// K2: fused attention. 1024 threads, IT=8 i-rows, JC=32 j-chunk,
// grid 128. Phase-1 2-score microtile; phase-2 4-il accumulators.
// ============================================================
#define IT 8
#define JC 32
#define GIS 544      // 8*68   per-h stride of s_gri
#define GLSH 2176    // 32*68  per-h stride of s_gl
#define EAS 264      // per-h stride of s_e / s_a

#define SMEM_FLOATS (4352 + 17408 + 16384 + 2112 + 2112 + 64 + 256 + 64)

__global__ __launch_bounds__(1024, 1) void k_attn(const float* __restrict__ attn_w,
                                                  const int* __restrict__ adj,
                                                  float* __restrict__ out) {
    extern __shared__ float sm[];
    float* s_gri = sm;                    // 4352 : [h][il*68 + f]
    float* s_gl  = s_gri + 4352;          // 17408: [h][jl*68 + f]
    float* s_gr  = s_gl + 17408;          // 16384: [jl][512]
    float* s_e   = s_gr + 16384;          // 2112 : [h][jl*8 + il]
    float* s_a   = s_e + 2112;            // 2112
    float* s_w   = s_a + 2112;            // 64  (0.4*w)
    float* s_el  = s_w + 64;              // 256 (0.6*el)
    float* s_er  = s_el + 256;            // 64  (0.6*er)
    ull*   s_red = (ull*)s_gl;            // aliased final-reduce buffer

    const int t  = threadIdx.x;
    const int b  = blockIdx.x >> 5;
    const int i0 = (blockIdx.x & 31) * IT;

    const float* Gl = g_gl + b * NN * HF;
    const float* Gr = g_gr + b * NN * HF;

    // phase-1 ids
    const int w1 = t >> 5, lane = t & 31;
    const int h1 = w1 >> 2;
    const int jh = (w1 >> 1) & 1;
    const int iq = w1 & 1;
    const int jl1  = jh * 16 + (lane & 15);
    const int il_a = iq * 2 + (lane >> 4);
    const int il_b = il_a + 4;
    // phase-2 ids
    const int ilh = t >> 9;
    const int jq  = (t >> 7) & 3;
    const int c4  = t & 127;
    const int h2  = c4 >> 4;

    // --- prologue ---
    if (t < 64) s_w[t] = 0.4f * attn_w[t];
    {
        const int il = t >> 7, rest = t & 127, h = rest >> 4, f4 = rest & 15;
        float4 v = *(const float4*)(Gr + (i0 + il) * 512 + rest * 4);
        *(float4*)(s_gri + h * GIS + il * 68 + f4 * 4) = v;
    }
    if (t < 64) s_er[t] = 0.6f * g_er[(b * NN + i0 + (t >> 3)) * 8 + (t & 7)];
    __syncthreads();

    const float era = s_er[il_a * 8 + h1];
    const float erb = s_er[il_b * 8 + h1];
    const ull ABSM = 0x7FFFFFFF7FFFFFFFULL;
    const float* pA = s_gri + h1 * GIS + il_a * 68;
    const float* pB = pA + 4 * 68;
    const float* pG = s_gl + h1 * GLSH + jl1 * 68;

    ull acc[4][2] = {};

    for (int jc = 0; jc < NN / JC; jc++) {
        const int j0 = jc * JC;

        // --- stage j-chunk (coalesced) ---
        #pragma unroll
        for (int q = 0; q < 4; q++) {
            const int idx = q * 1024 + t;
            const int jl = idx >> 7, rest = idx & 127;
            const int h = rest >> 4, f4 = rest & 15;
            float4 vl = *(const float4*)(Gl + (j0 + jl) * 512 + rest * 4);
            float4 vr = *(const float4*)(Gr + (j0 + jl) * 512 + rest * 4);
            *(float4*)(s_gl + h * GLSH + jl * 68 + f4 * 4) = vl;
            *(float4*)(s_gr + jl * 512 + rest * 4) = vr;
        }
        if (t < 256) s_el[t] = 0.6f * g_el[(b * NN + j0 + (t >> 3)) * 8 + (t & 7)];
        __syncthreads();

        // --- phase 1: two scores (il_a, il_b) x (j0+jl1) x h1 ---
        {
            ull s0a = 0, s1a = 0, s0b = 0, s1b = 0;
            #pragma unroll
            for (int f4 = 0; f4 < 16; f4++) {
                ulonglong2 Aa = *(const ulonglong2*)(pA + f4 * 4);
                ulonglong2 Ab = *(const ulonglong2*)(pB + f4 * 4);
                ulonglong2 Bv = *(const ulonglong2*)(pG + f4 * 4);
                ulonglong2 Wv = *(const ulonglong2*)(s_w + f4 * 4);
                s0a = f2fma(f2add(Aa.x, Bv.x) & ABSM, Wv.x, s0a);
                s1a = f2fma(f2add(Aa.y, Bv.y) & ABSM, Wv.y, s1a);
                s0b = f2fma(f2add(Ab.x, Bv.x) & ABSM, Wv.x, s0b);
                s1b = f2fma(f2add(Ab.y, Bv.y) & ABSM, Wv.y, s1b);
            }
            float2 a0 = upk(s0a), a1 = upk(s1a), b0 = upk(s0b), b1 = upk(s1b);
            const float elv = s_el[jl1 * 8 + h1];
            float ea = era + elv + ((a0.x + a0.y) + (a1.x + a1.y));
            float eb = erb + elv + ((b0.x + b0.y) + (b1.x + b1.y));
            const int j = j0 + jl1;
            const int ava = adj[((i0 + il_a) * NN + j) * HH + h1];
            const int avb = adj[((i0 + il_b) * NN + j) * HH + h1];
            ea = ava ? ea : -1e30f;
            eb = avb ? eb : -1e30f;
            s_e[h1 * EAS + jl1 * 8 + il_a] = ea;
            s_e[h1 * EAS + jl1 * 8 + il_b] = eb;
        }
        __syncthreads();

        // --- softmax over heads; one thread per (jl,il) pair ---
        if (t < 256) {
            float ev[8];
            #pragma unroll
            for (int h = 0; h < 8; h++) ev[h] = s_e[h * EAS + t];
            float m = ev[0];
            #pragma unroll
            for (int h = 1; h < 8; h++) m = fmaxf(m, ev[h]);
            float ps[8]; float sum = 0.f;
            #pragma unroll
            for (int h = 0; h < 8; h++) { ps[h] = __expf(ev[h] - m); sum += ps[h]; }
            const float rinv = __fdividef(1.0f, sum);
            #pragma unroll
            for (int h = 0; h < 8; h++) s_a[h * EAS + t] = ps[h] * rinv;
        }
        __syncthreads();

        // --- phase 2: 4 il rows, j-quarter jq, columns c4*4..+3 ---
        {
            const int jbase = jq * 8;
            #pragma unroll
            for (int jn = 0; jn < 8; jn++) {
                const int jl = jbase + jn;
                ulonglong2 g = *(const ulonglong2*)(s_gr + jl * 512 + c4 * 4);
                float4 a4 = *(const float4*)(s_a + h2 * EAS + jl * 8 + ilh * 4);
                ull p0 = pk(a4.x, a4.x), p1 = pk(a4.y, a4.y);
                ull p2 = pk(a4.z, a4.z), p3 = pk(a4.w, a4.w);
                acc[0][0] = f2fma(p0, g.x, acc[0][0]);
                acc[0][1] = f2fma(p0, g.y, acc[0][1]);
                acc[1][0] = f2fma(p1, g.x, acc[1][0]);
                acc[1][1] = f2fma(p1, g.y, acc[1][1]);
                acc[2][0] = f2fma(p2, g.x, acc[2][0]);
                acc[2][1] = f2fma(p2, g.y, acc[2][1]);
                acc[3][0] = f2fma(p3, g.x, acc[3][0]);
                acc[3][1] = f2fma(p3, g.y, acc[3][1]);
            }
        }
        __syncthreads();
    }

    // --- cross-jq reduce and store ---
    if (jq != 0) {
        ull* dst = s_red + ((jq - 1) * 2 + ilh) * 1024 + c4 * 8;
        #pragma unroll
        for (int il = 0; il < 4; il++) {
            dst[il * 2 + 0] = acc[il][0];
            dst[il * 2 + 1] = acc[il][1];
        }
    }
    __syncthreads();
    if (jq == 0) {
        #pragma unroll
        for (int g = 0; g < 3; g++) {
            const ull* src = s_red + (g * 2 + ilh) * 1024 + c4 * 8;
            #pragma unroll
            for (int il = 0; il < 4; il++) {
                acc[il][0] = f2add(acc[il][0], src[il * 2 + 0]);
                acc[il][1] = f2add(acc[il][1], src[il * 2 + 1]);
            }
        }
        #pragma unroll
        for (int il = 0; il < 4; il++) {
            float2 lo = upk(acc[il][0]), hi = upk(acc[il][1]);
            const int row = b * NN + i0 + ilh * 4 + il;
            *(float4*)(out + row * 512 + c4 * 4) = make_float4(lo.x, lo.y, hi.x, hi.y);
        }
    }
}

// ============================================================
extern "C" void kernel_launch(void* const* d_in, const int* in_sizes, int n_in,
                              void* d_out, int out_size) {
    (void)in_sizes; (void)n_in; (void)out_size;
    const float* x   = (const float*)d_in[0];
    const float* Wl  = (const float*)d_in[1];
    const float* Wr  = (const float*)d_in[2];
    const float* aw  = (const float*)d_in[3];
    const int*   adj = (const int*)d_in[4];
    float*       out = (float*)d_out;

    k_gemm<<<dim3(8, 32, 2), 256>>>(x, Wl, Wr, aw);

    const int smem_bytes = SMEM_FLOATS * (int)sizeof(float);
    cudaFuncSetAttribute(k_attn, cudaFuncAttributeMaxDynamicSharedMemorySize, smem_bytes);
    k_attn<<<128, 1024, smem_bytes>>>(aw, adj, out);
}

// round 5
// speedup vs baseline: 1.7010x; 1.1461x over previous
#include <cuda_runtime.h>
#include <math.h>

#define BB 4
#define NN 256
#define CC 256
#define HH 8
#define FF 64
#define HF 512

typedef unsigned long long ull;

__device__ float g_gl[BB * NN * HF];
__device__ float g_gr[BB * NN * HF];
__device__ float g_el[BB * NN * HH];     // 0.6 * dot(g_l, w)
__device__ float g_er[BB * NN * HH];     // 0.6 * dot(g_r, w)
__device__ float g_part[2][BB * NN * HF];
__device__ unsigned char g_mask[NN * NN];

// ---- packed f32x2 helpers ----
__device__ __forceinline__ ull f2add(ull a, ull b) {
    ull r; asm("add.rn.f32x2 %0,%1,%2;" : "=l"(r) : "l"(a), "l"(b)); return r;
}
__device__ __forceinline__ ull f2fma(ull a, ull b, ull c) {
    ull r; asm("fma.rn.f32x2 %0,%1,%2,%3;" : "=l"(r) : "l"(a), "l"(b), "l"(c)); return r;
}
__device__ __forceinline__ ull pk(float lo, float hi) {
    ull r; asm("mov.b64 %0,{%1,%2};" : "=l"(r) : "f"(lo), "f"(hi)); return r;
}
__device__ __forceinline__ float2 upk(ull v) {
    float2 r; asm("mov.b64 {%0,%1},%2;" : "=f"(r.x), "=f"(r.y) : "l"(v)); return r;
}

// ============================================================
// K1: SGEMM G = X[1024,256] @ W[256,512], 64x64 tile, 4x4 packed
// microtile, fused (0.6 * dot(g,w)) epilogue. grid (8,16,2).
// ============================================================
__global__ __launch_bounds__(256) void k_gemm(const float* __restrict__ X,
                                              const float* __restrict__ Wl,
                                              const float* __restrict__ Wr,
                                              const float* __restrict__ attn_w) {
    __shared__ float As[16][68];
    __shared__ float Bs[16][68];
    const int which = blockIdx.z;
    const float* W = which ? Wr : Wl;
    float* G = which ? g_gr : g_gl;
    float* E = which ? g_er : g_el;

    const int t  = threadIdx.x;
    // interleaved map: phase(16 lanes) covers 8 tx x 2 ty -> b broadcast in-phase
    const int tx = (t >> 1) & 15;
    const int ty = ((t & 1) << 3) | (t >> 5);
    const int m0 = blockIdx.y * 64;
    const int n0 = blockIdx.x * 64;

    ull acc[4][2] = {};

    for (int k0 = 0; k0 < 256; k0 += 16) {
        {   // stage X tile transposed
            const int m = t >> 2, kq = t & 3;
            float4 xa = *(const float4*)(X + (m0 + m) * 256 + k0 + kq * 4);
            As[kq * 4 + 0][m] = xa.x;
            As[kq * 4 + 1][m] = xa.y;
            As[kq * 4 + 2][m] = xa.z;
            As[kq * 4 + 3][m] = xa.w;
        }
        {   // stage W tile
            const int k = t >> 4, c = t & 15;
            *(float4*)(&Bs[k][c * 4]) =
                *(const float4*)(W + (k0 + k) * 512 + n0 + c * 4);
        }
        __syncthreads();
        #pragma unroll
        for (int k = 0; k < 16; k++) {
            float4 a4 = *(const float4*)(&As[k][ty * 4]);
            ulonglong2 b2 = *(const ulonglong2*)(&Bs[k][tx * 4]);
            ull p0 = pk(a4.x, a4.x), p1 = pk(a4.y, a4.y);
            ull p2 = pk(a4.z, a4.z), p3 = pk(a4.w, a4.w);
            acc[0][0] = f2fma(p0, b2.x, acc[0][0]);
            acc[0][1] = f2fma(p0, b2.y, acc[0][1]);
            acc[1][0] = f2fma(p1, b2.x, acc[1][0]);
            acc[1][1] = f2fma(p1, b2.y, acc[1][1]);
            acc[2][0] = f2fma(p2, b2.x, acc[2][0]);
            acc[2][1] = f2fma(p2, b2.y, acc[2][1]);
            acc[3][0] = f2fma(p3, b2.x, acc[3][0]);
            acc[3][1] = f2fma(p3, b2.y, acc[3][1]);
        }
        __syncthreads();
    }

    float af[4][4];
    #pragma unroll
    for (int i = 0; i < 4; i++) {
        float2 lo = upk(acc[i][0]), hi = upk(acc[i][1]);
        af[i][0] = lo.x; af[i][1] = lo.y; af[i][2] = hi.x; af[i][3] = hi.y;
        *(float4*)(G + (m0 + ty * 4 + i) * 512 + n0 + tx * 4) =
            make_float4(lo.x, lo.y, hi.x, hi.y);
    }

    // fused 0.6 * dot(g_row_head, w): n-tile is exactly one head
    const int hh = n0 >> 6;
    float w0 = attn_w[tx * 4 + 0], w1 = attn_w[tx * 4 + 1];
    float w2 = attn_w[tx * 4 + 2], w3 = attn_w[tx * 4 + 3];
    #pragma unroll
    for (int i = 0; i < 4; i++) {
        float part = af[i][0] * w0;
        part = fmaf(af[i][1], w1, part);
        part = fmaf(af[i][2], w2, part);
        part = fmaf(af[i][3], w3, part);
        // reduce over tx = lane bits 1..4
        part += __shfl_xor_sync(0xffffffff, part, 16);
        part += __shfl_xor_sync(0xffffffff, part, 8);
        part += __shfl_xor_sync(0xffffffff, part, 4);
        part += __shfl_xor_sync(0xffffffff, part, 2);
        if (tx == 0) E[(m0 + ty * 4 + i) * 8 + hh] = 0.6f * part;
    }
}

// ============================================================
// K1c: pack adj int32 [N,N,8] -> byte mask [N,N]
// ============================================================
__global__ __launch_bounds__(256) void k_pack(const int* __restrict__ adj) {
    const int idx = blockIdx.x * 256 + threadIdx.x;   // 0..65535
    const int4* A = (const int4*)adj;
    int4 x0 = A[idx * 2], x1 = A[idx * 2 + 1];
    unsigned m = (x0.x != 0)
               | ((x0.y != 0) << 1) | ((x0.z != 0) << 2) | ((x0.w != 0) << 3)
               | ((x1.x != 0) << 4) | ((x1.y != 0) << 5) | ((x1.z != 0) << 6)
               | ((x1.w != 0) << 7);
    g_mask[idx] = (unsigned char)m;
}

// ============================================================
// K2: fused attention, 512 threads, IT=8 i-rows, j-half per block,
// JC=16. grid = 4b x 32it x 2jh = 256 (-> 2 blocks/SM).
// ============================================================
#define IT 8
#define JC 16
#define GIS 544      // 8*68  s_gri per-h stride
#define GLSH 1088    // 16*68 s_gl per-h stride
#define SAS 136      // s_a per-h stride

#define SMEM_FLOATS (4352 + 8704 + 8192 + 1152 + 1088 + 64 + 128 + 64)

__global__ __launch_bounds__(512, 2) void k_attn(const float* __restrict__ attn_w) {
    extern __shared__ float sm[];
    float* s_gri = sm;                   // [h][il*68+f]        4352
    float* s_gl  = s_gri + 4352;         // [h][jl*68+f4s*4]    8704
    float* s_gr  = s_gl + 8704;          // [jl][512]           8192
    float* s_e   = s_gr + 8192;          // [(il*16+jl)*9+h]    1152
    float* s_a   = s_e + 1152;           // [h][jl*8+il]        1088
    float* s_w   = s_a + 1088;           // 0.4*w               64
    float* s_el  = s_w + 64;             // 128
    float* s_er  = s_el + 128;           // 64
    ull*   s_red = (ull*)s_gl;           // aliased reduce buf

    const int t  = threadIdx.x;
    const int bx = blockIdx.x;
    const int jh = bx & 1;
    const int it = (bx >> 1) & 31;
    const int b  = bx >> 6;
    const int i0 = it * IT;
    const int jbase = jh * 128;

    const float* Gl = g_gl + b * NN * HF;
    const float* Gr = g_gr + b * NN * HF;

    // phase-1 ids: warp = h (x2 warps per h), phase holds 8 jl x 2 il
    const int w1 = t >> 5, lane = t & 31;
    const int h1  = w1 >> 1;
    const int ilq = w1 & 1;
    const int il_a = ilq * 2 + (lane & 1);
    const int il_b = il_a + 4;
    const int jl1  = lane >> 1;
    const int fx   = (jl1 >> 3) << 2;     // smem f4 swizzle
    // phase-2 ids
    const int c4  = t & 127;
    const int ilh = (t >> 7) & 1;
    const int jq  = t >> 8;
    const int h2  = c4 >> 4;

    // prologue
    if (t < 64) s_w[t] = 0.4f * attn_w[t];
    #pragma unroll
    for (int q = 0; q < 2; q++) {
        const int idx = q * 512 + t;
        const int il = idx >> 7, rest = idx & 127, h = rest >> 4, f4 = rest & 15;
        float4 v = *(const float4*)(Gr + (i0 + il) * 512 + rest * 4);
        *(float4*)(s_gri + h * GIS + il * 68 + f4 * 4) = v;
    }
    if (t < 64) s_er[t] = g_er[(b * NN + i0 + (t >> 3)) * 8 + (t & 7)];
    __syncthreads();

    const float era = s_er[il_a * 8 + h1];
    const float erb = s_er[il_b * 8 + h1];
    const ull ABSM = 0x7FFFFFFF7FFFFFFFULL;
    const float* pA = s_gri + h1 * GIS + il_a * 68;
    const float* pB = pA + 4 * 68;
    const float* pG = s_gl + h1 * GLSH + jl1 * 68;

    ull acc[4][2] = {};

    for (int jc = 0; jc < 8; jc++) {
        const int j0 = jbase + jc * JC;

        // stage j-chunk
        #pragma unroll
        for (int q = 0; q < 4; q++) {
            const int idx = q * 512 + t;
            const int jl = idx >> 7, rest = idx & 127;
            const int h = rest >> 4, f4 = rest & 15;
            const int f4s = f4 ^ ((jl >> 3) << 2);
            float4 vl = *(const float4*)(Gl + (j0 + jl) * 512 + rest * 4);
            float4 vr = *(const float4*)(Gr + (j0 + jl) * 512 + rest * 4);
            *(float4*)(s_gl + h * GLSH + jl * 68 + f4s * 4) = vl;
            *(float4*)(s_gr + jl * 512 + rest * 4) = vr;
        }
        if (t < 128) s_el[t] = g_el[(b * NN + j0 + (t >> 3)) * 8 + (t & 7)];
        __syncthreads();

        // phase 1: scores for (il_a, il_b) x (j0+jl1) x h1
        {
            ull s0a = 0, s1a = 0, s0b = 0, s1b = 0;
            #pragma unroll
            for (int k = 0; k < 16; k++) {
                const int c = k ^ fx;   // logical chunk held at position k
                ulonglong2 Bv = *(const ulonglong2*)(pG + k * 4);
                ulonglong2 Aa = *(const ulonglong2*)(pA + c * 4);
                ulonglong2 Ab = *(const ulonglong2*)(pB + c * 4);
                ulonglong2 Wv = *(const ulonglong2*)(s_w + c * 4);
                s0a = f2fma(f2add(Aa.x, Bv.x) & ABSM, Wv.x, s0a);
                s1a = f2fma(f2add(Aa.y, Bv.y) & ABSM, Wv.y, s1a);
                s0b = f2fma(f2add(Ab.x, Bv.x) & ABSM, Wv.x, s0b);
                s1b = f2fma(f2add(Ab.y, Bv.y) & ABSM, Wv.y, s1b);
            }
            float2 a0 = upk(s0a), a1 = upk(s1a), b0 = upk(s0b), b1 = upk(s1b);
            const float elv = s_el[jl1 * 8 + h1];
            float ea = era + elv + ((a0.x + a0.y) + (a1.x + a1.y));
            float eb = erb + elv + ((b0.x + b0.y) + (b1.x + b1.y));
            const int j = j0 + jl1;
            const unsigned ma = g_mask[(i0 + il_a) * NN + j];
            const unsigned mb = g_mask[(i0 + il_b) * NN + j];
            ea = ((ma >> h1) & 1) ? ea : -1e30f;
            eb = ((mb >> h1) & 1) ? eb : -1e30f;
            s_e[(il_a * 16 + jl1) * 9 + h1] = ea;
            s_e[(il_b * 16 + jl1) * 9 + h1] = eb;
        }
        __syncthreads();

        // softmax over heads: t<128, pair = (il = t>>4, jl = t&15)
        if (t < 128) {
            const int il = t >> 4, jl = t & 15;
            float ev[8];
            #pragma unroll
            for (int h = 0; h < 8; h++) ev[h] = s_e[t * 9 + h];
            float m = ev[0];
            #pragma unroll
            for (int h = 1; h < 8; h++) m = fmaxf(m, ev[h]);
            float ps[8]; float sum = 0.f;
            #pragma unroll
            for (int h = 0; h < 8; h++) { ps[h] = __expf(ev[h] - m); sum += ps[h]; }
            const float rinv = __fdividef(1.0f, sum);
            #pragma unroll
            for (int h = 0; h < 8; h++) s_a[h * SAS + jl * 8 + il] = ps[h] * rinv;
        }
        __syncthreads();

        // phase 2: thread = (jq j-half, ilh il-quad, c4 cols), 4 il accs
        {
            const int jb = jq * 8;
            #pragma unroll
            for (int jn = 0; jn < 8; jn++) {
                const int jl = jb + jn;
                ulonglong2 g = *(const ulonglong2*)(s_gr + jl * 512 + c4 * 4);
                float4 a4 = *(const float4*)(s_a + h2 * SAS + jl * 8 + ilh * 4);
                ull p0 = pk(a4.x, a4.x), p1 = pk(a4.y, a4.y);
                ull p2 = pk(a4.z, a4.z), p3 = pk(a4.w, a4.w);
                acc[0][0] = f2fma(p0, g.x, acc[0][0]);
                acc[0][1] = f2fma(p0, g.y, acc[0][1]);
                acc[1][0] = f2fma(p1, g.x, acc[1][0]);
                acc[1][1] = f2fma(p1, g.y, acc[1][1]);
                acc[2][0] = f2fma(p2, g.x, acc[2][0]);
                acc[2][1] = f2fma(p2, g.y, acc[2][1]);
                acc[3][0] = f2fma(p3, g.x, acc[3][0]);
                acc[3][1] = f2fma(p3, g.y, acc[3][1]);
            }
        }
        __syncthreads();
    }

    // cross-jq reduce, write partial
    if (jq == 1) {
        ull* dst = s_red + (t - 256) * 8;
        #pragma unroll
        for (int il = 0; il < 4; il++) {
            dst[il * 2 + 0] = acc[il][0];
            dst[il * 2 + 1] = acc[il][1];
        }
    }
    __syncthreads();
    if (jq == 0) {
        const ull* src = s_red + t * 8;
        float* P = g_part[jh];
        #pragma unroll
        for (int il = 0; il < 4; il++) {
            float2 lo = upk(f2add(acc[il][0], src[il * 2 + 0]));
            float2 hi = upk(f2add(acc[il][1], src[il * 2 + 1]));
            const int row = b * NN + i0 + ilh * 4 + il;
            *(float4*)(P + row * 512 + c4 * 4) = make_float4(lo.x, lo.y, hi.x, hi.y);
        }
    }
}

// ============================================================
// K3: out = part0 + part1   (131072 float4s total)
// ============================================================
__global__ __launch_bounds__(512) void k_reduce(float* __restrict__ out) {
    const int idx = blockIdx.x * 512 + threadIdx.x;   // 0..131071
    const float4* p0 = (const float4*)g_part[0];
    const float4* p1 = (const float4*)g_part[1];
    float4 a = p0[idx], c = p1[idx];
    ((float4*)out)[idx] = make_float4(a.x + c.x, a.y + c.y, a.z + c.z, a.w + c.w);
}

// ============================================================
extern "C" void kernel_launch(void* const* d_in, const int* in_sizes, int n_in,
                              void* d_out, int out_size) {
    (void)in_sizes; (void)n_in; (void)out_size;
    const float* x   = (const float*)d_in[0];
    const float* Wl  = (const float*)d_in[1];
    const float* Wr  = (const float*)d_in[2];
    const float* aw  = (const float*)d_in[3];
    const int*   adj = (const int*)d_in[4];
    float*       out = (float*)d_out;

    k_gemm<<<dim3(8, 16, 2), 256>>>(x, Wl, Wr, aw);
    k_pack<<<256, 256>>>(adj);

    const int smem_bytes = SMEM_FLOATS * (int)sizeof(float);
    cudaFuncSetAttribute(k_attn, cudaFuncAttributeMaxDynamicSharedMemorySize, smem_bytes);
    k_attn<<<256, 512, smem_bytes>>>(aw);

    k_reduce<<<256, 512>>>(out);
}